// round 8
// baseline (speedup 1.0000x reference)
#include <cuda_runtime.h>
#include <cuda_bf16.h>
#include <math.h>
#include <stdint.h>

#define NB       8192      // batch B
#define E_DIM    1024
#define P_DIM    512
#define D_DIM    1024      // 2P
#define M2       16384     // 2B rows in projection GEMM

// Scratch (no allocations allowed)
__device__ float g_zn[(size_t)NB * D_DIM];              // 32 MB fp32 (proj output)
__device__ __nv_bfloat16 g_znh[(size_t)NB * D_DIM];     // 16 MB bf16 normalized
__device__ __nv_bfloat16 g_xh[(size_t)NB * 2 * E_DIM];  // 32 MB bf16 relu(x)
__device__ __nv_bfloat16 g_wh[(size_t)E_DIM * P_DIM];   // 1 MB bf16 w
__device__ float g_rowsum[NB];
__device__ float g_pos[NB];

// ---------------------------------------------------------------------------
// PTX helpers (sm_80-era only)
// ---------------------------------------------------------------------------
__device__ __forceinline__ uint32_t smem_u32(const void* p) {
    uint32_t a;
    asm("{ .reg .u64 t; cvta.to.shared.u64 t, %1; cvt.u32.u64 %0, t; }" : "=r"(a) : "l"(p));
    return a;
}
__device__ __forceinline__ void cp_async16(uint32_t dst, const void* src) {
    asm volatile("cp.async.cg.shared.global [%0], [%1], 16;" :: "r"(dst), "l"(src));
}
#define CP_COMMIT() asm volatile("cp.async.commit_group;" ::: "memory")
#define CP_WAIT(N)  asm volatile("cp.async.wait_group %0;" :: "n"(N) : "memory")

__device__ __forceinline__ void ldsm_x4(uint32_t& r0, uint32_t& r1, uint32_t& r2,
                                        uint32_t& r3, uint32_t addr) {
    asm volatile("ldmatrix.sync.aligned.m8n8.x4.shared.b16 {%0,%1,%2,%3}, [%4];"
                 : "=r"(r0), "=r"(r1), "=r"(r2), "=r"(r3) : "r"(addr));
}
__device__ __forceinline__ void ldsm_x4_t(uint32_t& r0, uint32_t& r1, uint32_t& r2,
                                          uint32_t& r3, uint32_t addr) {
    asm volatile("ldmatrix.sync.aligned.m8n8.x4.trans.shared.b16 {%0,%1,%2,%3}, [%4];"
                 : "=r"(r0), "=r"(r1), "=r"(r2), "=r"(r3) : "r"(addr));
}
__device__ __forceinline__ void mma_bf16(float* c, const uint32_t* a, const uint32_t* b) {
    asm volatile(
        "mma.sync.aligned.m16n8k16.row.col.f32.bf16.bf16.f32 "
        "{%0,%1,%2,%3}, {%4,%5,%6,%7}, {%8,%9}, {%0,%1,%2,%3};"
        : "+f"(c[0]), "+f"(c[1]), "+f"(c[2]), "+f"(c[3])
        : "r"(a[0]), "r"(a[1]), "r"(a[2]), "r"(a[3]), "r"(b[0]), "r"(b[1]));
}

// ---------------------------------------------------------------------------
// Kernel 0: convert relu(x)->bf16 (g_xh) and w->bf16 (g_wh)
// ---------------------------------------------------------------------------
#define XCVT_BLOCKS 16384
#define WCVT_BLOCKS 512
__global__ __launch_bounds__(256) void convert_kernel(const float* __restrict__ x,
                                                      const float* __restrict__ w) {
    const int tid = threadIdx.x;
    if (blockIdx.x < XCVT_BLOCKS) {
        const size_t i = ((size_t)blockIdx.x * 256 + tid);
        float4 v = *(const float4*)(x + i * 4);
        __nv_bfloat162 p0 = __floats2bfloat162_rn(fmaxf(v.x, 0.f), fmaxf(v.y, 0.f));
        __nv_bfloat162 p1 = __floats2bfloat162_rn(fmaxf(v.z, 0.f), fmaxf(v.w, 0.f));
        uint2 o; o.x = *(uint32_t*)&p0; o.y = *(uint32_t*)&p1;
        *(uint2*)(g_xh + i * 4) = o;
    } else {
        const size_t i = ((size_t)(blockIdx.x - XCVT_BLOCKS) * 256 + tid);
        float4 v = *(const float4*)(w + i * 4);
        __nv_bfloat162 p0 = __floats2bfloat162_rn(v.x, v.y);
        __nv_bfloat162 p1 = __floats2bfloat162_rn(v.z, v.w);
        uint2 o; o.x = *(uint32_t*)&p0; o.y = *(uint32_t*)&p1;
        *(uint2*)(g_wh + i * 4) = o;
    }
}

// ---------------------------------------------------------------------------
// Kernel 1: HMMA projection, block 128x128, 4 warps (warp tile 64x64),
// BK=32, 4 stages, 2 chunks per wait/sync, batched fragment loads.
// ---------------------------------------------------------------------------
#define AROW_BYTES  80
#define PA_BYTES    (128 * AROW_BYTES)       // 10240
#define BROW_BYTES  272                      // 128 bf16 + 16B pad
#define PB_BYTES    (32 * BROW_BYTES)        // 8704
#define PSTAGE      (PA_BYTES + PB_BYTES)    // 18944
#define PSTAGES     4
#define PROJ_SMEM   (PSTAGES * PSTAGE)       // 75776
#define PCHUNKS     (E_DIM / 32)             // 32

extern __shared__ char dsmem[];

__device__ __forceinline__ void proj_prefetch(uint32_t stA, uint32_t stB,
                                              int m0, int n0, int kb, int tid) {
#pragma unroll
    for (int it = 0; it < 4; it++) {        // A: 128 rows x 4 segs
        const int j = tid + it * 128;
        const int row = j >> 2, seg = j & 3;
        const int r = m0 + row;
        const __nv_bfloat16* src = g_xh + (size_t)(r & (NB - 1)) * 2048
                                 + (size_t)(r >> 13) * 1024 + kb + (seg << 3);
        cp_async16(stA + row * AROW_BYTES + seg * 16, src);
    }
#pragma unroll
    for (int it = 0; it < 4; it++) {        // B: 32 k-rows x 16 segs
        const int j = tid + it * 128;
        const int row = j >> 4, seg = j & 15;
        const __nv_bfloat16* src = g_wh + (size_t)(kb + row) * P_DIM + n0 + (seg << 3);
        cp_async16(stB + row * BROW_BYTES + seg * 16, src);
    }
}

__global__ __launch_bounds__(128)
void proj_kernel(const float* __restrict__ bias) {
    const int tid = threadIdx.x;
    const int wid = tid >> 5;
    const int lane = tid & 31;
    const int warp_m = wid >> 1;
    const int warp_n = wid & 1;
    const int m0 = blockIdx.y * 128;
    const int n0 = blockIdx.x * 128;

    const uint32_t sbase = smem_u32(dsmem);
    uint32_t stA[PSTAGES], stB[PSTAGES];
#pragma unroll
    for (int s = 0; s < PSTAGES; s++) {
        stA[s] = sbase + s * PSTAGE;
        stB[s] = stA[s] + PA_BYTES;
    }

    const uint32_t aOff = (warp_m * 64 + (lane & 15)) * AROW_BYTES + (lane >> 4) * 16;
    const uint32_t bRow = (lane & 7) + ((lane >> 3) & 1) * 8;
    const uint32_t bCol = warp_n * 64 + (lane >> 4) * 8;

    float acc[4][8][4];
#pragma unroll
    for (int mi = 0; mi < 4; mi++)
#pragma unroll
        for (int ni = 0; ni < 8; ni++)
#pragma unroll
            for (int k = 0; k < 4; k++) acc[mi][ni][k] = 0.f;

    proj_prefetch(stA[0], stB[0], m0, n0, 0, tid);
    proj_prefetch(stA[1], stB[1], m0, n0, 32, tid);
    CP_COMMIT();

    for (int it = 0; it < PCHUNKS / 2; it++) {
        const int kc0 = it * 2;
        CP_WAIT(0);
        __syncthreads();
        if (kc0 + 2 < PCHUNKS) {
            proj_prefetch(stA[(kc0 + 2) & 3], stB[(kc0 + 2) & 3], m0, n0, (kc0 + 2) * 32, tid);
            proj_prefetch(stA[(kc0 + 3) & 3], stB[(kc0 + 3) & 3], m0, n0, (kc0 + 3) * 32, tid);
        }
        CP_COMMIT();

#pragma unroll
        for (int cc = 0; cc < 2; cc++) {
            const int s = (kc0 + cc) & 3;
            uint32_t aF[2][4][4], bF[2][4][4];
#pragma unroll
            for (int ks = 0; ks < 2; ks++) {
#pragma unroll
                for (int mi = 0; mi < 4; mi++)
                    ldsm_x4(aF[ks][mi][0], aF[ks][mi][1], aF[ks][mi][2], aF[ks][mi][3],
                            stA[s] + aOff + mi * 16 * AROW_BYTES + ks * 32);
#pragma unroll
                for (int p = 0; p < 4; p++)
                    ldsm_x4_t(bF[ks][p][0], bF[ks][p][1], bF[ks][p][2], bF[ks][p][3],
                              stB[s] + (ks * 16 + bRow) * BROW_BYTES + (bCol + p * 16) * 2);
            }
#pragma unroll
            for (int ks = 0; ks < 2; ks++)
#pragma unroll
                for (int mi = 0; mi < 4; mi++)
#pragma unroll
                    for (int ni = 0; ni < 8; ni++)
                        mma_bf16(acc[mi][ni], aF[ks][mi], &bF[ks][ni >> 1][(ni & 1) * 2]);
        }
    }

    // epilogue: + bias, store fp32 to g_zn (interleaved layout)
    const int cb = n0 + warp_n * 64 + (lane & 3) * 2;
#pragma unroll
    for (int mi = 0; mi < 4; mi++)
#pragma unroll
        for (int half8 = 0; half8 < 2; half8++) {
            const int r = m0 + warp_m * 64 + mi * 16 + half8 * 8 + (lane >> 2);
            const int ib = r & (NB - 1);
            const int hh = r >> 13;
            float* outRow = g_zn + (size_t)ib * D_DIM + hh * P_DIM;
#pragma unroll
            for (int ni = 0; ni < 8; ni++) {
                const int c = cb + ni * 8;
                float2 v;
                v.x = acc[mi][ni][half8 * 2 + 0] + __ldg(bias + c);
                v.y = acc[mi][ni][half8 * 2 + 1] + __ldg(bias + c + 1);
                *(float2*)(outRow + c) = v;
            }
        }
}

// ---------------------------------------------------------------------------
// Kernel 2: per-row L2 normalize -> bf16 g_znh (also zeroes g_rowsum)
// ---------------------------------------------------------------------------
__global__ __launch_bounds__(256) void norm_kernel() {
    __shared__ float red[256];
    const float* row = g_zn + (size_t)blockIdx.x * D_DIM;
    float4 v = *(const float4*)(row + threadIdx.x * 4);
    red[threadIdx.x] = v.x * v.x + v.y * v.y + v.z * v.z + v.w * v.w;
    __syncthreads();
    for (int off = 128; off > 0; off >>= 1) {
        if (threadIdx.x < off) red[threadIdx.x] += red[threadIdx.x + off];
        __syncthreads();
    }
    const float inv = 1.0f / fmaxf(sqrtf(red[0]), 1e-8f);
    __nv_bfloat162 p0 = __floats2bfloat162_rn(v.x * inv, v.y * inv);
    __nv_bfloat162 p1 = __floats2bfloat162_rn(v.z * inv, v.w * inv);
    uint2 o; o.x = *(uint32_t*)&p0; o.y = *(uint32_t*)&p1;
    *(uint2*)(g_znh + (size_t)blockIdx.x * D_DIM + threadIdx.x * 4) = o;
    if (threadIdx.x == 0) g_rowsum[blockIdx.x] = 0.f;
}

// ---------------------------------------------------------------------------
// Kernel 3: HMMA sim GEMM (upper triangle), block 128x128, 4 warps (64x64),
// 4 stages, 2 chunks per wait/sync, batched fragment loads, fused softmax.
// ---------------------------------------------------------------------------
#define ROW_BYTES   80
#define TILE_BYTES  (128 * ROW_BYTES)
#define STAGE_BYTES (2 * TILE_BYTES)
#define SSTAGES     4
#define SIM_SMEM    (SSTAGES * STAGE_BYTES)  // 81920
#define NUM_CHUNKS  (D_DIM / 32)
#define TRI_BLOCKS  2080

__device__ __forceinline__ void sim_prefetch(uint32_t stageA, uint32_t stageB,
                                             int r0, int c0, int kb, int tid) {
#pragma unroll
    for (int it = 0; it < 4; it++) {
        const int i = tid + it * 128;
        const int row = i >> 2, seg = i & 3;
        const uint32_t d = row * ROW_BYTES + seg * 16;
        cp_async16(stageA + d, g_znh + (((size_t)(r0 + row)) << 10) + kb + (seg << 3));
        cp_async16(stageB + d, g_znh + (((size_t)(c0 + row)) << 10) + kb + (seg << 3));
    }
}

__global__ __launch_bounds__(128)
void sim_kernel() {
    // map t -> (by, bx) upper triangle, bx >= by
    const int t = blockIdx.x;
    int by = (int)((129.0f - sqrtf(129.0f * 129.0f - 8.0f * (float)t)) * 0.5f);
    if (by > 63) by = 63;
    if (by < 0) by = 0;
    while (by * 64 - (by * (by - 1)) / 2 > t) by--;
    while ((by + 1) * 64 - ((by + 1) * by) / 2 <= t) by++;
    const int bx = by + (t - (by * 64 - (by * (by - 1)) / 2));

    const int tid = threadIdx.x;
    const int wid = tid >> 5;
    const int lane = tid & 31;
    const int warp_m = wid >> 1;
    const int warp_n = wid & 1;
    const int r0 = by * 128;
    const int c0 = bx * 128;

    const uint32_t sbase = smem_u32(dsmem);
    uint32_t stA[SSTAGES], stB[SSTAGES];
#pragma unroll
    for (int s = 0; s < SSTAGES; s++) {
        stA[s] = sbase + s * STAGE_BYTES;
        stB[s] = stA[s] + TILE_BYTES;
    }

    const uint32_t aOff = (warp_m * 64 + (lane & 15)) * ROW_BYTES + (lane >> 4) * 16;
    const uint32_t bOff = (warp_n * 64 + ((lane >> 4) & 1) * 8 + (lane & 7)) * ROW_BYTES
                        + ((lane >> 3) & 1) * 16;

    float acc[4][8][4];
#pragma unroll
    for (int mi = 0; mi < 4; mi++)
#pragma unroll
        for (int ni = 0; ni < 8; ni++)
#pragma unroll
            for (int k = 0; k < 4; k++) acc[mi][ni][k] = 0.f;

    sim_prefetch(stA[0], stB[0], r0, c0, 0, tid);
    sim_prefetch(stA[1], stB[1], r0, c0, 32, tid);
    CP_COMMIT();

    for (int it = 0; it < NUM_CHUNKS / 2; it++) {
        const int kc0 = it * 2;
        CP_WAIT(0);
        __syncthreads();
        if (kc0 + 2 < NUM_CHUNKS) {
            sim_prefetch(stA[(kc0 + 2) & 3], stB[(kc0 + 2) & 3], r0, c0, (kc0 + 2) * 32, tid);
            sim_prefetch(stA[(kc0 + 3) & 3], stB[(kc0 + 3) & 3], r0, c0, (kc0 + 3) * 32, tid);
        }
        CP_COMMIT();

#pragma unroll
        for (int cc = 0; cc < 2; cc++) {
            const int s = (kc0 + cc) & 3;
            uint32_t aF[2][4][4], bF[2][4][4];
#pragma unroll
            for (int ks = 0; ks < 2; ks++) {
#pragma unroll
                for (int mi = 0; mi < 4; mi++)
                    ldsm_x4(aF[ks][mi][0], aF[ks][mi][1], aF[ks][mi][2], aF[ks][mi][3],
                            stA[s] + aOff + mi * 16 * ROW_BYTES + ks * 32);
#pragma unroll
                for (int p = 0; p < 4; p++)
                    ldsm_x4(bF[ks][p][0], bF[ks][p][1], bF[ks][p][2], bF[ks][p][3],
                            stB[s] + bOff + p * 16 * ROW_BYTES + ks * 32);
            }
#pragma unroll
            for (int ks = 0; ks < 2; ks++)
#pragma unroll
                for (int mi = 0; mi < 4; mi++)
#pragma unroll
                    for (int ni = 0; ni < 8; ni++)
                        mma_bf16(acc[mi][ni], aF[ks][mi], &bF[ks][ni >> 1][(ni & 1) * 2]);
        }
    }

    // ---------------- fused epilogue ----------------
    const bool isDiag = (bx == by);
    const bool hasPos = (bx == (by ^ 32));
    const int rb = r0 + warp_m * 64 + (lane >> 2);
    const int cb = c0 + warp_n * 64 + (lane & 3) * 2;

#pragma unroll
    for (int mi = 0; mi < 4; mi++)
#pragma unroll
        for (int ni = 0; ni < 8; ni++)
#pragma unroll
            for (int k = 0; k < 4; k++) {
                const int r = rb + mi * 16 + (k >> 1) * 8;
                const int c = cb + ni * 8 + (k & 1);
                const float logit = acc[mi][ni][k] * 10.0f;
                if (hasPos && c == (r ^ 4096)) { g_pos[r] = logit; g_pos[c] = logit; }
                float ev = __expf(logit - 10.0f);
                if (isDiag && r == c) ev = 0.f;
                acc[mi][ni][k] = ev;
            }

    // row sums
    float rs[4][2];
#pragma unroll
    for (int mi = 0; mi < 4; mi++) { rs[mi][0] = 0.f; rs[mi][1] = 0.f; }
#pragma unroll
    for (int mi = 0; mi < 4; mi++)
#pragma unroll
        for (int ni = 0; ni < 8; ni++) {
            rs[mi][0] += acc[mi][ni][0] + acc[mi][ni][1];
            rs[mi][1] += acc[mi][ni][2] + acc[mi][ni][3];
        }
#pragma unroll
    for (int off = 1; off <= 2; off <<= 1)
#pragma unroll
        for (int mi = 0; mi < 4; mi++)
#pragma unroll
            for (int h = 0; h < 2; h++)
                rs[mi][h] += __shfl_xor_sync(0xffffffffu, rs[mi][h], off);
    {
        const int mi = lane & 3;
        const int r = r0 + warp_m * 64 + mi * 16 + (lane >> 2);
        atomicAdd(&g_rowsum[r],     rs[mi][0]);
        atomicAdd(&g_rowsum[r + 8], rs[mi][1]);
    }

    // column sums (symmetric contribution), off-diag blocks only
    if (!isDiag) {
        float cs[8][2];
#pragma unroll
        for (int ni = 0; ni < 8; ni++) {
            cs[ni][0] = 0.f; cs[ni][1] = 0.f;
#pragma unroll
            for (int mi = 0; mi < 4; mi++) {
                cs[ni][0] += acc[mi][ni][0] + acc[mi][ni][2];
                cs[ni][1] += acc[mi][ni][1] + acc[mi][ni][3];
            }
        }
#pragma unroll
        for (int off = 4; off <= 16; off <<= 1)
#pragma unroll
            for (int ni = 0; ni < 8; ni++)
#pragma unroll
                for (int h = 0; h < 2; h++)
                    cs[ni][h] += __shfl_xor_sync(0xffffffffu, cs[ni][h], off);
        const int ni = lane >> 2;
        atomicAdd(&g_rowsum[cb + ni * 8 + 0], cs[ni][0]);
        atomicAdd(&g_rowsum[cb + ni * 8 + 1], cs[ni][1]);
    }
}

// ---------------------------------------------------------------------------
// Kernel 4: nll_i = -pos_i + 10 + log(rowsum_i); out = mean(nll)
// ---------------------------------------------------------------------------
__global__ __launch_bounds__(256) void final_kernel(float* __restrict__ out) {
    __shared__ float red[256];
    float s = 0.f;
    for (int i = threadIdx.x; i < NB; i += 256)
        s += -g_pos[i] + 10.0f + logf(g_rowsum[i]);
    red[threadIdx.x] = s;
    __syncthreads();
    for (int off = 128; off > 0; off >>= 1) {
        if (threadIdx.x < off) red[threadIdx.x] += red[threadIdx.x + off];
        __syncthreads();
    }
    if (threadIdx.x == 0) out[0] = red[0] / (float)NB;
}

// ---------------------------------------------------------------------------
extern "C" void kernel_launch(void* const* d_in, const int* in_sizes, int n_in,
                              void* d_out, int out_size) {
    const float* x = (const float*)d_in[0];
    const float* w = (const float*)d_in[1];
    const float* b = (const float*)d_in[2];
    float* out = (float*)d_out;

    cudaFuncSetAttribute(proj_kernel, cudaFuncAttributeMaxDynamicSharedMemorySize, PROJ_SMEM);
    cudaFuncSetAttribute(sim_kernel,  cudaFuncAttributeMaxDynamicSharedMemorySize, SIM_SMEM);

    convert_kernel<<<XCVT_BLOCKS + WCVT_BLOCKS, 256>>>(x, w);
    dim3 g1(P_DIM / 128, M2 / 128);
    proj_kernel<<<g1, 128, PROJ_SMEM>>>(b);
    norm_kernel<<<NB, 256>>>();
    sim_kernel<<<TRI_BLOCKS, 128, SIM_SMEM>>>();
    final_kernel<<<1, 256>>>(out);
}

// round 9
// speedup vs baseline: 1.1734x; 1.1734x over previous
#include <cuda_runtime.h>
#include <cuda_bf16.h>
#include <math.h>
#include <stdint.h>

#define NB       8192      // batch B
#define E_DIM    1024
#define P_DIM    512
#define D_DIM    1024      // 2P
#define M2       16384     // 2B rows in projection GEMM

// Scratch (no allocations allowed)
__device__ __nv_bfloat16 g_zb[(size_t)NB * D_DIM];      // 16 MB bf16 proj output z
__device__ __nv_bfloat16 g_znh[(size_t)NB * D_DIM];     // 16 MB bf16 normalized
__device__ __nv_bfloat16 g_xh[(size_t)NB * 2 * E_DIM];  // 32 MB bf16 relu(x)
__device__ __nv_bfloat16 g_wh[(size_t)E_DIM * P_DIM];   // 1 MB bf16 w
__device__ float g_rowsum[NB];
__device__ float g_pos[NB];

// ---------------------------------------------------------------------------
// PTX helpers (sm_80-era only)
// ---------------------------------------------------------------------------
__device__ __forceinline__ uint32_t smem_u32(const void* p) {
    uint32_t a;
    asm("{ .reg .u64 t; cvta.to.shared.u64 t, %1; cvt.u32.u64 %0, t; }" : "=r"(a) : "l"(p));
    return a;
}
__device__ __forceinline__ void cp_async16(uint32_t dst, const void* src) {
    asm volatile("cp.async.cg.shared.global [%0], [%1], 16;" :: "r"(dst), "l"(src));
}
#define CP_COMMIT() asm volatile("cp.async.commit_group;" ::: "memory")
#define CP_WAIT(N)  asm volatile("cp.async.wait_group %0;" :: "n"(N) : "memory")

__device__ __forceinline__ void ldsm_x4(uint32_t& r0, uint32_t& r1, uint32_t& r2,
                                        uint32_t& r3, uint32_t addr) {
    asm volatile("ldmatrix.sync.aligned.m8n8.x4.shared.b16 {%0,%1,%2,%3}, [%4];"
                 : "=r"(r0), "=r"(r1), "=r"(r2), "=r"(r3) : "r"(addr));
}
__device__ __forceinline__ void ldsm_x4_t(uint32_t& r0, uint32_t& r1, uint32_t& r2,
                                          uint32_t& r3, uint32_t addr) {
    asm volatile("ldmatrix.sync.aligned.m8n8.x4.trans.shared.b16 {%0,%1,%2,%3}, [%4];"
                 : "=r"(r0), "=r"(r1), "=r"(r2), "=r"(r3) : "r"(addr));
}
__device__ __forceinline__ void mma_bf16(float* c, const uint32_t* a, const uint32_t* b) {
    asm volatile(
        "mma.sync.aligned.m16n8k16.row.col.f32.bf16.bf16.f32 "
        "{%0,%1,%2,%3}, {%4,%5,%6,%7}, {%8,%9}, {%0,%1,%2,%3};"
        : "+f"(c[0]), "+f"(c[1]), "+f"(c[2]), "+f"(c[3])
        : "r"(a[0]), "r"(a[1]), "r"(a[2]), "r"(a[3]), "r"(b[0]), "r"(b[1]));
}

// ---------------------------------------------------------------------------
// Kernel 0: convert relu(x)->bf16 (g_xh) and w->bf16 (g_wh)
// ---------------------------------------------------------------------------
#define XCVT_BLOCKS 16384
#define WCVT_BLOCKS 512
__global__ __launch_bounds__(256) void convert_kernel(const float* __restrict__ x,
                                                      const float* __restrict__ w) {
    const int tid = threadIdx.x;
    if (blockIdx.x < XCVT_BLOCKS) {
        const size_t i = ((size_t)blockIdx.x * 256 + tid);
        float4 v = *(const float4*)(x + i * 4);
        __nv_bfloat162 p0 = __floats2bfloat162_rn(fmaxf(v.x, 0.f), fmaxf(v.y, 0.f));
        __nv_bfloat162 p1 = __floats2bfloat162_rn(fmaxf(v.z, 0.f), fmaxf(v.w, 0.f));
        uint2 o; o.x = *(uint32_t*)&p0; o.y = *(uint32_t*)&p1;
        *(uint2*)(g_xh + i * 4) = o;
    } else {
        const size_t i = ((size_t)(blockIdx.x - XCVT_BLOCKS) * 256 + tid);
        float4 v = *(const float4*)(w + i * 4);
        __nv_bfloat162 p0 = __floats2bfloat162_rn(v.x, v.y);
        __nv_bfloat162 p1 = __floats2bfloat162_rn(v.z, v.w);
        uint2 o; o.x = *(uint32_t*)&p0; o.y = *(uint32_t*)&p1;
        *(uint2*)(g_wh + i * 4) = o;
    }
}

// ---------------------------------------------------------------------------
// Kernel 1: HMMA projection (R7 structure), block 128x128, 4 warps (64x64),
// BK=32, 4-stage cp.async, WAIT(2), batched fragment loads. bf16 output.
// ---------------------------------------------------------------------------
#define AROW_BYTES  80
#define PA_BYTES    (128 * AROW_BYTES)       // 10240
#define BROW_BYTES  272                      // 128 bf16 + 16B pad
#define PB_BYTES    (32 * BROW_BYTES)        // 8704
#define PSTAGE      (PA_BYTES + PB_BYTES)    // 18944
#define PSTAGES     4
#define PROJ_SMEM   (PSTAGES * PSTAGE)       // 75776
#define PCHUNKS     (E_DIM / 32)             // 32

extern __shared__ char dsmem[];

__device__ __forceinline__ void proj_prefetch(uint32_t stA, uint32_t stB,
                                              int m0, int n0, int kb, int tid) {
#pragma unroll
    for (int it = 0; it < 4; it++) {        // A: 128 rows x 4 segs
        const int j = tid + it * 128;
        const int row = j >> 2, seg = j & 3;
        const int r = m0 + row;
        const __nv_bfloat16* src = g_xh + (size_t)(r & (NB - 1)) * 2048
                                 + (size_t)(r >> 13) * 1024 + kb + (seg << 3);
        cp_async16(stA + row * AROW_BYTES + seg * 16, src);
    }
#pragma unroll
    for (int it = 0; it < 4; it++) {        // B: 32 k-rows x 16 segs
        const int j = tid + it * 128;
        const int row = j >> 4, seg = j & 15;
        const __nv_bfloat16* src = g_wh + (size_t)(kb + row) * P_DIM + n0 + (seg << 3);
        cp_async16(stB + row * BROW_BYTES + seg * 16, src);
    }
}

__global__ __launch_bounds__(128)
void proj_kernel(const float* __restrict__ bias) {
    const int tid = threadIdx.x;
    const int wid = tid >> 5;
    const int lane = tid & 31;
    const int warp_m = wid >> 1;
    const int warp_n = wid & 1;
    const int m0 = blockIdx.y * 128;
    const int n0 = blockIdx.x * 128;

    const uint32_t sbase = smem_u32(dsmem);
    uint32_t stA[PSTAGES], stB[PSTAGES];
#pragma unroll
    for (int s = 0; s < PSTAGES; s++) {
        stA[s] = sbase + s * PSTAGE;
        stB[s] = stA[s] + PA_BYTES;
    }

    const uint32_t aOff = (warp_m * 64 + (lane & 15)) * AROW_BYTES + (lane >> 4) * 16;
    const uint32_t bRow = (lane & 7) + ((lane >> 3) & 1) * 8;
    const uint32_t bCol = warp_n * 64 + (lane >> 4) * 8;

    float acc[4][8][4];
#pragma unroll
    for (int mi = 0; mi < 4; mi++)
#pragma unroll
        for (int ni = 0; ni < 8; ni++)
#pragma unroll
            for (int k = 0; k < 4; k++) acc[mi][ni][k] = 0.f;

    proj_prefetch(stA[0], stB[0], m0, n0, 0, tid);  CP_COMMIT();
    proj_prefetch(stA[1], stB[1], m0, n0, 32, tid); CP_COMMIT();
    proj_prefetch(stA[2], stB[2], m0, n0, 64, tid); CP_COMMIT();

    for (int kc = 0; kc < PCHUNKS; kc++) {
        CP_WAIT(2);
        __syncthreads();
        const int s = kc % PSTAGES;

        uint32_t aF[2][4][4], bF[2][4][4];
#pragma unroll
        for (int ks = 0; ks < 2; ks++) {
#pragma unroll
            for (int mi = 0; mi < 4; mi++)
                ldsm_x4(aF[ks][mi][0], aF[ks][mi][1], aF[ks][mi][2], aF[ks][mi][3],
                        stA[s] + aOff + mi * 16 * AROW_BYTES + ks * 32);
#pragma unroll
            for (int p = 0; p < 4; p++)
                ldsm_x4_t(bF[ks][p][0], bF[ks][p][1], bF[ks][p][2], bF[ks][p][3],
                          stB[s] + (ks * 16 + bRow) * BROW_BYTES + (bCol + p * 16) * 2);
        }

        if (kc + 3 < PCHUNKS) {
            const int sn = (kc + 3) % PSTAGES;
            proj_prefetch(stA[sn], stB[sn], m0, n0, (kc + 3) * 32, tid);
        }
        CP_COMMIT();

#pragma unroll
        for (int ks = 0; ks < 2; ks++)
#pragma unroll
            for (int mi = 0; mi < 4; mi++)
#pragma unroll
                for (int ni = 0; ni < 8; ni++)
                    mma_bf16(acc[mi][ni], aF[ks][mi], &bF[ks][ni >> 1][(ni & 1) * 2]);
    }

    // epilogue: + bias, store bf16 to g_zb (interleaved layout)
    const int cb = n0 + warp_n * 64 + (lane & 3) * 2;
#pragma unroll
    for (int mi = 0; mi < 4; mi++)
#pragma unroll
        for (int half8 = 0; half8 < 2; half8++) {
            const int r = m0 + warp_m * 64 + mi * 16 + half8 * 8 + (lane >> 2);
            const int ib = r & (NB - 1);
            const int hh = r >> 13;
            __nv_bfloat16* outRow = g_zb + (size_t)ib * D_DIM + hh * P_DIM;
#pragma unroll
            for (int ni = 0; ni < 8; ni++) {
                const int c = cb + ni * 8;
                __nv_bfloat162 v = __floats2bfloat162_rn(
                    acc[mi][ni][half8 * 2 + 0] + __ldg(bias + c),
                    acc[mi][ni][half8 * 2 + 1] + __ldg(bias + c + 1));
                *(uint32_t*)(outRow + c) = *(uint32_t*)&v;
            }
        }
}

// ---------------------------------------------------------------------------
// Kernel 2: per-row L2 normalize (bf16 in) -> bf16 g_znh, zeroes g_rowsum
// ---------------------------------------------------------------------------
__global__ __launch_bounds__(256) void norm_kernel() {
    __shared__ float red[256];
    const __nv_bfloat16* row = g_zb + (size_t)blockIdx.x * D_DIM;
    uint2 u = *(const uint2*)(row + threadIdx.x * 4);
    __nv_bfloat162 b0 = *(__nv_bfloat162*)&u.x;
    __nv_bfloat162 b1 = *(__nv_bfloat162*)&u.y;
    float v0 = __bfloat162float(b0.x), v1 = __bfloat162float(b0.y);
    float v2 = __bfloat162float(b1.x), v3 = __bfloat162float(b1.y);
    red[threadIdx.x] = v0 * v0 + v1 * v1 + v2 * v2 + v3 * v3;
    __syncthreads();
    for (int off = 128; off > 0; off >>= 1) {
        if (threadIdx.x < off) red[threadIdx.x] += red[threadIdx.x + off];
        __syncthreads();
    }
    const float inv = 1.0f / fmaxf(sqrtf(red[0]), 1e-8f);
    __nv_bfloat162 p0 = __floats2bfloat162_rn(v0 * inv, v1 * inv);
    __nv_bfloat162 p1 = __floats2bfloat162_rn(v2 * inv, v3 * inv);
    uint2 o; o.x = *(uint32_t*)&p0; o.y = *(uint32_t*)&p1;
    *(uint2*)(g_znh + (size_t)blockIdx.x * D_DIM + threadIdx.x * 4) = o;
    if (threadIdx.x == 0) g_rowsum[blockIdx.x] = 0.f;
}

// ---------------------------------------------------------------------------
// Kernel 3: HMMA sim GEMM (upper triangle), block 128x128, 4 warps (64x64),
// BK=64, 3 stages, WAIT(1), ks-pair batched fragment loads, fused softmax.
// ---------------------------------------------------------------------------
#define SROW_BYTES  144                       // 64 bf16 (128B) + 16B pad
#define STILE_BYTES (128 * SROW_BYTES)        // 18432
#define SST_BYTES   (2 * STILE_BYTES)         // 36864
#define SSTAGES     3
#define SIM_SMEM    (SSTAGES * SST_BYTES)     // 110592
#define SCHUNKS     (D_DIM / 64)              // 16
#define TRI_BLOCKS  2080

__device__ __forceinline__ void sim_prefetch(uint32_t stageA, uint32_t stageB,
                                             int r0, int c0, int kb, int tid) {
#pragma unroll
    for (int it = 0; it < 8; it++) {
        const int i = tid + it * 128;
        const int row = i >> 3, seg = i & 7;
        const uint32_t d = row * SROW_BYTES + seg * 16;
        cp_async16(stageA + d, g_znh + (((size_t)(r0 + row)) << 10) + kb + (seg << 3));
        cp_async16(stageB + d, g_znh + (((size_t)(c0 + row)) << 10) + kb + (seg << 3));
    }
}

__global__ __launch_bounds__(128)
void sim_kernel() {
    // map t -> (by, bx) upper triangle, bx >= by
    const int t = blockIdx.x;
    int by = (int)((129.0f - sqrtf(129.0f * 129.0f - 8.0f * (float)t)) * 0.5f);
    if (by > 63) by = 63;
    if (by < 0) by = 0;
    while (by * 64 - (by * (by - 1)) / 2 > t) by--;
    while ((by + 1) * 64 - ((by + 1) * by) / 2 <= t) by++;
    const int bx = by + (t - (by * 64 - (by * (by - 1)) / 2));

    const int tid = threadIdx.x;
    const int wid = tid >> 5;
    const int lane = tid & 31;
    const int warp_m = wid >> 1;
    const int warp_n = wid & 1;
    const int r0 = by * 128;
    const int c0 = bx * 128;

    const uint32_t sbase = smem_u32(dsmem);
    uint32_t stA[SSTAGES], stB[SSTAGES];
#pragma unroll
    for (int s = 0; s < SSTAGES; s++) {
        stA[s] = sbase + s * SST_BYTES;
        stB[s] = stA[s] + STILE_BYTES;
    }

    const uint32_t aOff = (warp_m * 64 + (lane & 15)) * SROW_BYTES + (lane >> 4) * 16;
    const uint32_t bOff = (warp_n * 64 + ((lane >> 4) & 1) * 8 + (lane & 7)) * SROW_BYTES
                        + ((lane >> 3) & 1) * 16;

    float acc[4][8][4];
#pragma unroll
    for (int mi = 0; mi < 4; mi++)
#pragma unroll
        for (int ni = 0; ni < 8; ni++)
#pragma unroll
            for (int k = 0; k < 4; k++) acc[mi][ni][k] = 0.f;

    sim_prefetch(stA[0], stB[0], r0, c0, 0, tid);  CP_COMMIT();
    sim_prefetch(stA[1], stB[1], r0, c0, 64, tid); CP_COMMIT();

    for (int kc = 0; kc < SCHUNKS; kc++) {
        CP_WAIT(1);
        __syncthreads();
        const int s = kc % SSTAGES;

        uint32_t aF[2][4][4], bF[2][4][4];
        // ks pair 0 (k-steps 0,1)
#pragma unroll
        for (int ks = 0; ks < 2; ks++) {
#pragma unroll
            for (int mi = 0; mi < 4; mi++)
                ldsm_x4(aF[ks][mi][0], aF[ks][mi][1], aF[ks][mi][2], aF[ks][mi][3],
                        stA[s] + aOff + mi * 16 * SROW_BYTES + ks * 32);
#pragma unroll
            for (int p = 0; p < 4; p++)
                ldsm_x4(bF[ks][p][0], bF[ks][p][1], bF[ks][p][2], bF[ks][p][3],
                        stB[s] + bOff + p * 16 * SROW_BYTES + ks * 32);
        }

        if (kc + 2 < SCHUNKS) {
            const int sn = (kc + 2) % SSTAGES;
            sim_prefetch(stA[sn], stB[sn], r0, c0, (kc + 2) * 64, tid);
        }
        CP_COMMIT();

#pragma unroll
        for (int ks = 0; ks < 2; ks++)
#pragma unroll
            for (int mi = 0; mi < 4; mi++)
#pragma unroll
                for (int ni = 0; ni < 8; ni++)
                    mma_bf16(acc[mi][ni], aF[ks][mi], &bF[ks][ni >> 1][(ni & 1) * 2]);

        // ks pair 1 (k-steps 2,3), reuse fragment registers
#pragma unroll
        for (int ks = 0; ks < 2; ks++) {
#pragma unroll
            for (int mi = 0; mi < 4; mi++)
                ldsm_x4(aF[ks][mi][0], aF[ks][mi][1], aF[ks][mi][2], aF[ks][mi][3],
                        stA[s] + aOff + mi * 16 * SROW_BYTES + (ks + 2) * 32);
#pragma unroll
            for (int p = 0; p < 4; p++)
                ldsm_x4(bF[ks][p][0], bF[ks][p][1], bF[ks][p][2], bF[ks][p][3],
                        stB[s] + bOff + p * 16 * SROW_BYTES + (ks + 2) * 32);
        }
#pragma unroll
        for (int ks = 0; ks < 2; ks++)
#pragma unroll
            for (int mi = 0; mi < 4; mi++)
#pragma unroll
                for (int ni = 0; ni < 8; ni++)
                    mma_bf16(acc[mi][ni], aF[ks][mi], &bF[ks][ni >> 1][(ni & 1) * 2]);
    }

    // ---------------- fused epilogue ----------------
    const bool isDiag = (bx == by);
    const bool hasPos = (bx == (by ^ 32));
    const int rb = r0 + warp_m * 64 + (lane >> 2);
    const int cb = c0 + warp_n * 64 + (lane & 3) * 2;

#pragma unroll
    for (int mi = 0; mi < 4; mi++)
#pragma unroll
        for (int ni = 0; ni < 8; ni++)
#pragma unroll
            for (int k = 0; k < 4; k++) {
                const int r = rb + mi * 16 + (k >> 1) * 8;
                const int c = cb + ni * 8 + (k & 1);
                const float logit = acc[mi][ni][k] * 10.0f;
                if (hasPos && c == (r ^ 4096)) { g_pos[r] = logit; g_pos[c] = logit; }
                float ev = __expf(logit - 10.0f);
                if (isDiag && r == c) ev = 0.f;
                acc[mi][ni][k] = ev;
            }

    // row sums
    float rs[4][2];
#pragma unroll
    for (int mi = 0; mi < 4; mi++) { rs[mi][0] = 0.f; rs[mi][1] = 0.f; }
#pragma unroll
    for (int mi = 0; mi < 4; mi++)
#pragma unroll
        for (int ni = 0; ni < 8; ni++) {
            rs[mi][0] += acc[mi][ni][0] + acc[mi][ni][1];
            rs[mi][1] += acc[mi][ni][2] + acc[mi][ni][3];
        }
#pragma unroll
    for (int off = 1; off <= 2; off <<= 1)
#pragma unroll
        for (int mi = 0; mi < 4; mi++)
#pragma unroll
            for (int h = 0; h < 2; h++)
                rs[mi][h] += __shfl_xor_sync(0xffffffffu, rs[mi][h], off);
    {
        const int mi = lane & 3;
        const int r = r0 + warp_m * 64 + mi * 16 + (lane >> 2);
        atomicAdd(&g_rowsum[r],     rs[mi][0]);
        atomicAdd(&g_rowsum[r + 8], rs[mi][1]);
    }

    // column sums (symmetric contribution), off-diag blocks only
    if (!isDiag) {
        float cs[8][2];
#pragma unroll
        for (int ni = 0; ni < 8; ni++) {
            cs[ni][0] = 0.f; cs[ni][1] = 0.f;
#pragma unroll
            for (int mi = 0; mi < 4; mi++) {
                cs[ni][0] += acc[mi][ni][0] + acc[mi][ni][2];
                cs[ni][1] += acc[mi][ni][1] + acc[mi][ni][3];
            }
        }
#pragma unroll
        for (int off = 4; off <= 16; off <<= 1)
#pragma unroll
            for (int ni = 0; ni < 8; ni++)
#pragma unroll
                for (int h = 0; h < 2; h++)
                    cs[ni][h] += __shfl_xor_sync(0xffffffffu, cs[ni][h], off);
        const int ni = lane >> 2;
        atomicAdd(&g_rowsum[cb + ni * 8 + 0], cs[ni][0]);
        atomicAdd(&g_rowsum[cb + ni * 8 + 1], cs[ni][1]);
    }
}

// ---------------------------------------------------------------------------
// Kernel 4: nll_i = -pos_i + 10 + log(rowsum_i); out = mean(nll)
// ---------------------------------------------------------------------------
__global__ __launch_bounds__(256) void final_kernel(float* __restrict__ out) {
    __shared__ float red[256];
    float s = 0.f;
    for (int i = threadIdx.x; i < NB; i += 256)
        s += -g_pos[i] + 10.0f + logf(g_rowsum[i]);
    red[threadIdx.x] = s;
    __syncthreads();
    for (int off = 128; off > 0; off >>= 1) {
        if (threadIdx.x < off) red[threadIdx.x] += red[threadIdx.x + off];
        __syncthreads();
    }
    if (threadIdx.x == 0) out[0] = red[0] / (float)NB;
}

// ---------------------------------------------------------------------------
extern "C" void kernel_launch(void* const* d_in, const int* in_sizes, int n_in,
                              void* d_out, int out_size) {
    const float* x = (const float*)d_in[0];
    const float* w = (const float*)d_in[1];
    const float* b = (const float*)d_in[2];
    float* out = (float*)d_out;

    cudaFuncSetAttribute(proj_kernel, cudaFuncAttributeMaxDynamicSharedMemorySize, PROJ_SMEM);
    cudaFuncSetAttribute(sim_kernel,  cudaFuncAttributeMaxDynamicSharedMemorySize, SIM_SMEM);

    convert_kernel<<<XCVT_BLOCKS + WCVT_BLOCKS, 256>>>(x, w);
    dim3 g1(P_DIM / 128, M2 / 128);
    proj_kernel<<<g1, 128, PROJ_SMEM>>>(b);
    norm_kernel<<<NB, 256>>>();
    sim_kernel<<<TRI_BLOCKS, 128, SIM_SMEM>>>();
    final_kernel<<<1, 256>>>(out);
}